// round 7
// baseline (speedup 1.0000x reference)
#include <cuda_runtime.h>
#include <cuda_bf16.h>

// RNN_72541997629806: 5-layer stacked LSTM (H=4), SEQ=610, BATCH=128,
// per-t Linear(4->1) + final FC [5,610] -> out [128,5].
//
// R7: one warp = TWO batch elements (streams A/B share per-lane weights),
//   branch-free systolic pipeline, gate dots in packed fma.rn.f32x2.
//   lane = stage*4 + j: stages 0-4 LSTM layers, stage 5 Linear+FC,
//   lanes 28-31 x-injection. 7 shuffles of hpub per stream per step.
//   x + w_fc staged in SMEM (zero-padded; no LDG, no selects in steady loop).

#define SEQ 610
#define BATCH 128
#define NSTEP (SEQ + 5)      // ss = 0 .. 614

typedef unsigned long long ull;

__device__ __forceinline__ float tanh_fast(float x) {
    float y;
    asm("tanh.approx.f32 %0, %1;" : "=f"(y) : "f"(x));
    return y;
}
__device__ __forceinline__ ull pk2(float lo, float hi) {
    ull r;
    asm("mov.b64 %0, {%1, %2};" : "=l"(r) : "f"(lo), "f"(hi));
    return r;
}
__device__ __forceinline__ ull fma2(ull a, ull b, ull c) {
    ull d;
    asm("fma.rn.f32x2 %0, %1, %2, %3;" : "=l"(d) : "l"(a), "l"(b), "l"(c));
    return d;
}
__device__ __forceinline__ float hadd2(ull v) {
    float lo, hi;
    asm("mov.b64 {%0, %1}, %2;" : "=f"(lo), "=f"(hi) : "l"(v));
    return lo + hi;
}

__global__ __launch_bounds__(32, 1)
void lstm_warp_kernel(const float* __restrict__ x,      // [128,610,2]
                      const float* __restrict__ w_ih0,  // [16,2]
                      const float* __restrict__ w_ih,   // [4,16,4]
                      const float* __restrict__ w_hh,   // [5,16,4]
                      const float* __restrict__ b_ih,   // [5,16]
                      const float* __restrict__ b_hh,   // [5,16]
                      const float* __restrict__ w_lin,  // [1,4]
                      const float* __restrict__ b_lin,  // [1]
                      const float* __restrict__ w_fc,   // [5,610]
                      const float* __restrict__ b_fc,   // [5]
                      float* __restrict__ out)          // [128,5]
{
    const int lane  = threadIdx.x;
    const int stage = lane >> 2;             // 0..7
    const int j     = lane & 3;
    const int bA    = blockIdx.x * 2;
    const int bB    = bA + 1;
    const int pbase = (lane - 4) & 28;       // base lane of previous stage quad
    const bool isX  = (lane >= 28);

    // ---- packed per-lane weights (shared by both streams) ----
    // wiA/wiB multiply (p0,p1)/(p2,p3); whA/whB multiply (h0,h1)/(h2,h3);
    // bias packed (b, 0). i/f/o gates pre-scaled by 0.5 (sigmoid-via-tanh).
    ull wiA0=0,wiA1=0,wiA2=0,wiA3=0, wiB0=0,wiB1=0,wiB2=0,wiB3=0;
    ull whA0=0,whA1=0,whA2=0,whA3=0, whB0=0,whB1=0,whB2=0,whB3=0;
    ull bp0=0, bp1=0, bp2=0, bp3=0;

    if (stage <= 4) {
        #define LQ(q, WIA, WIB, WHA, WHB, BP) do {                                 \
            const int   r  = (q) * 4 + j;                                          \
            const float sc = ((q) == 2) ? 1.0f : 0.5f;                             \
            float w0, w1, w2, w3;                                                  \
            if (stage == 0) {                                                      \
                w0 = sc * w_ih0[r * 2 + 0];  w1 = sc * w_ih0[r * 2 + 1];           \
                w2 = 0.0f;                   w3 = 0.0f;                            \
            } else {                                                               \
                const float* wp = w_ih + (((stage - 1) * 16) + r) * 4;             \
                w0 = sc * wp[0]; w1 = sc * wp[1]; w2 = sc * wp[2]; w3 = sc * wp[3];\
            }                                                                      \
            WIA = pk2(w0, w1);  WIB = pk2(w2, w3);                                 \
            const float* hp = w_hh + ((stage * 16) + r) * 4;                       \
            WHA = pk2(sc * hp[j ^ 0], sc * hp[j ^ 1]);                             \
            WHB = pk2(sc * hp[j ^ 2], sc * hp[j ^ 3]);                             \
            BP  = pk2(sc * (b_ih[stage * 16 + r] + b_hh[stage * 16 + r]), 0.0f);   \
        } while (0)
        LQ(0, wiA0, wiB0, whA0, whB0, bp0);
        LQ(1, wiA1, wiB1, whA1, whB1, bp1);
        LQ(2, wiA2, wiB2, whA2, whB2, bp2);
        LQ(3, wiA3, wiB3, whA3, whB3, bp3);
        #undef LQ
    } else if (stage == 5) {
        wiA0 = pk2(w_lin[0], w_lin[1]);
        wiB0 = pk2(w_lin[2], w_lin[3]);
        bp0  = pk2(b_lin[0], 0.0f);
    }

    // ---- SMEM staging ----
    __shared__ float2 xs2[2][SEQ + 8];           // per-stream x row, zero-padded
    __shared__ float  wfc_s[5][SEQ + 16];        // row idx ss: [5..614]=w_fc[ss-5]
    {
        const float2* xbA = reinterpret_cast<const float2*>(x + (size_t)bA * SEQ * 2);
        const float2* xbB = reinterpret_cast<const float2*>(x + (size_t)bB * SEQ * 2);
        for (int i = lane; i < SEQ + 8; i += 32) {
            xs2[0][i] = (i < SEQ) ? xbA[i] : make_float2(0.0f, 0.0f);
            xs2[1][i] = (i < SEQ) ? xbB[i] : make_float2(0.0f, 0.0f);
        }
        #pragma unroll
        for (int r = 0; r < 5; ++r)
            for (int i = lane; i < SEQ + 16; i += 32)
                wfc_s[r][i] = (i >= 5 && i < SEQ + 5) ? w_fc[r * SEQ + (i - 5)] : 0.0f;
    }
    __syncwarp();

    const float* wR = wfc_s[(stage == 5) ? j : 0];   // per-lane FC row
    const float* w4 = wfc_s[4];

    // ---- per-stream state ----
    float hpA = (lane == 28) ? xs2[0][0].x : ((lane == 29) ? xs2[0][0].y : 0.0f);
    float hpB = (lane == 28) ? xs2[1][0].x : ((lane == 29) ? xs2[1][0].y : 0.0f);
    float cjA = 0.0f, cjB = 0.0f;
    float accA_A = (stage == 5) ? b_fc[j] : 0.0f;
    float accA_B = accA_A;
    float accB_A = (lane == 20) ? b_fc[4] : 0.0f;
    float accB_B = accB_A;

    // one stream's sub-step: HP=hpub reg, CJ=c reg, AA/AB=acc regs, XS=x row
    #define SUBSTEP(ss, GUARD, HP, CJ, AA, AB, XS, WFA, WF4) do {                  \
        const float2 xv = (XS)[(ss) + 1];                                          \
        const float h0 = HP;                                                       \
        const float h1 = __shfl_xor_sync(0xffffffffu, HP, 1);                      \
        const float h2 = __shfl_xor_sync(0xffffffffu, HP, 2);                      \
        const float h3 = __shfl_xor_sync(0xffffffffu, HP, 3);                      \
        const float p0 = __shfl_sync(0xffffffffu, HP, pbase);                      \
        const float p1 = __shfl_sync(0xffffffffu, HP, pbase + 1);                  \
        const float p2 = __shfl_sync(0xffffffffu, HP, pbase + 2);                  \
        const float p3 = __shfl_sync(0xffffffffu, HP, pbase + 3);                  \
        const ull hA = pk2(h0, h1), hB = pk2(h2, h3);                              \
        const ull pA = pk2(p0, p1), pB = pk2(p2, p3);                              \
        const float g0 = hadd2(fma2(whB0, hB, fma2(whA0, hA,                       \
                               fma2(wiB0, pB, fma2(wiA0, pA, bp0)))));             \
        const float g1 = hadd2(fma2(whB1, hB, fma2(whA1, hA,                       \
                               fma2(wiB1, pB, fma2(wiA1, pA, bp1)))));             \
        const float g2 = hadd2(fma2(whB2, hB, fma2(whA2, hA,                       \
                               fma2(wiB2, pB, fma2(wiA2, pA, bp2)))));             \
        const float g3 = hadd2(fma2(whB3, hB, fma2(whA3, hA,                       \
                               fma2(wiB3, pB, fma2(wiA3, pA, bp3)))));             \
        const float gt = tanh_fast(g2);                                            \
        const float ig = fmaf(0.5f, tanh_fast(g0), 0.5f);                          \
        const float fg = fmaf(0.5f, tanh_fast(g1), 0.5f);                          \
        const float og = fmaf(0.5f, tanh_fast(g3), 0.5f);                          \
        const float cn = fmaf(fg, CJ, ig * gt);                                    \
        const float hn = og * tanh_fast(cn);                                       \
        float xc = (lane & 1) ? xv.y : xv.x;                                       \
        xc = (lane & 2) ? 0.0f : xc;                                               \
        if (GUARD) {                                                               \
            const bool tv = (unsigned)((ss) - stage) < (unsigned)SEQ;              \
            CJ = tv ? cn : CJ;                                                     \
            const float hc = tv ? hn : HP;                                         \
            HP = isX ? xc : hc;                                                    \
        } else {                                                                   \
            CJ = cn;                                                               \
            HP = isX ? xc : hn;                                                    \
        }                                                                          \
        AA = fmaf((WFA), g0, AA);                                                  \
        AB = fmaf((WF4), g0, AB);                                                  \
    } while (0)

    #define STEP(ss, GUARD) do {                                                   \
        const float wfa = wR[(ss)];                                                \
        const float wf4 = w4[(ss)];                                                \
        SUBSTEP(ss, GUARD, hpA, cjA, accA_A, accB_A, xs2[0], wfa, wf4);            \
        SUBSTEP(ss, GUARD, hpB, cjB, accA_B, accB_B, xs2[1], wfa, wf4);            \
    } while (0)

    #pragma unroll 1
    for (int ss = 0; ss < 5; ++ss) STEP(ss, true);
    #pragma unroll 1
    for (int ss = 5; ss < NSTEP; ++ss) STEP(ss, false);

    #undef STEP
    #undef SUBSTEP

    if (stage == 5) {
        out[bA * 5 + j] = accA_A;
        out[bB * 5 + j] = accA_B;
    }
    if (lane == 20) {
        out[bA * 5 + 4] = accB_A;
        out[bB * 5 + 4] = accB_B;
    }
}

extern "C" void kernel_launch(void* const* d_in, const int* in_sizes, int n_in,
                              void* d_out, int out_size) {
    const float* x     = (const float*)d_in[0];
    const float* w_ih0 = (const float*)d_in[1];
    const float* w_ih  = (const float*)d_in[2];
    const float* w_hh  = (const float*)d_in[3];
    const float* b_ih  = (const float*)d_in[4];
    const float* b_hh  = (const float*)d_in[5];
    const float* w_lin = (const float*)d_in[6];
    const float* b_lin = (const float*)d_in[7];
    const float* w_fc  = (const float*)d_in[8];
    const float* b_fc  = (const float*)d_in[9];
    float* out = (float*)d_out;

    lstm_warp_kernel<<<BATCH / 2, 32>>>(
        x, w_ih0, w_ih, w_hh, b_ih, b_hh, w_lin, b_lin, w_fc, b_fc, out);
}

// round 8
// speedup vs baseline: 1.4256x; 1.4256x over previous
#include <cuda_runtime.h>
#include <cuda_bf16.h>

// RNN_72541997629806: 5-layer stacked LSTM (H=4), SEQ=610, BATCH=128,
// per-t Linear(4->1) + final FC [5,610] -> out [128,5].
//
// R8: one warp = ONE batch element (128 blocks — full SM coverage, the
//   R7 lesson), branch-free systolic pipeline, gate dots in packed
//   fma.rn.f32x2 (R7's per-stream win). lane = stage*4 + j: stages 0-4
//   LSTM layers, stage 5 Linear+FC, lanes 28-31 x-injection.
//   x + w_fc staged in SMEM (zero-padded); select-free steady loop.

#define SEQ 610
#define BATCH 128
#define NSTEP (SEQ + 5)      // ss = 0 .. 614

typedef unsigned long long ull;

__device__ __forceinline__ float tanh_fast(float x) {
    float y;
    asm("tanh.approx.f32 %0, %1;" : "=f"(y) : "f"(x));
    return y;
}
__device__ __forceinline__ ull pk2(float lo, float hi) {
    ull r;
    asm("mov.b64 %0, {%1, %2};" : "=l"(r) : "f"(lo), "f"(hi));
    return r;
}
__device__ __forceinline__ ull fma2(ull a, ull b, ull c) {
    ull d;
    asm("fma.rn.f32x2 %0, %1, %2, %3;" : "=l"(d) : "l"(a), "l"(b), "l"(c));
    return d;
}
__device__ __forceinline__ float hadd2(ull v) {
    float lo, hi;
    asm("mov.b64 {%0, %1}, %2;" : "=f"(lo), "=f"(hi) : "l"(v));
    return lo + hi;
}

__global__ __launch_bounds__(32, 1)
void lstm_warp_kernel(const float* __restrict__ x,      // [128,610,2]
                      const float* __restrict__ w_ih0,  // [16,2]
                      const float* __restrict__ w_ih,   // [4,16,4]
                      const float* __restrict__ w_hh,   // [5,16,4]
                      const float* __restrict__ b_ih,   // [5,16]
                      const float* __restrict__ b_hh,   // [5,16]
                      const float* __restrict__ w_lin,  // [1,4]
                      const float* __restrict__ b_lin,  // [1]
                      const float* __restrict__ w_fc,   // [5,610]
                      const float* __restrict__ b_fc,   // [5]
                      float* __restrict__ out)          // [128,5]
{
    const int lane  = threadIdx.x;
    const int stage = lane >> 2;             // 0..7
    const int j     = lane & 3;
    const int b     = blockIdx.x;
    const int pbase = (lane - 4) & 28;       // base lane of previous stage quad
    const bool isX  = (lane >= 28);

    // ---- packed per-lane weights ----
    // wiA/wiB multiply (p0,p1)/(p2,p3); whA/whB multiply (h0,h1)/(h2,h3);
    // bias packed (b, 0). i/f/o gates pre-scaled by 0.5 (sigmoid-via-tanh).
    ull wiA0=0,wiA1=0,wiA2=0,wiA3=0, wiB0=0,wiB1=0,wiB2=0,wiB3=0;
    ull whA0=0,whA1=0,whA2=0,whA3=0, whB0=0,whB1=0,whB2=0,whB3=0;
    ull bp0=0, bp1=0, bp2=0, bp3=0;

    if (stage <= 4) {
        #define LQ(q, WIA, WIB, WHA, WHB, BP) do {                                 \
            const int   r  = (q) * 4 + j;                                          \
            const float sc = ((q) == 2) ? 1.0f : 0.5f;                             \
            float w0, w1, w2, w3;                                                  \
            if (stage == 0) {                                                      \
                w0 = sc * w_ih0[r * 2 + 0];  w1 = sc * w_ih0[r * 2 + 1];           \
                w2 = 0.0f;                   w3 = 0.0f;                            \
            } else {                                                               \
                const float* wp = w_ih + (((stage - 1) * 16) + r) * 4;             \
                w0 = sc * wp[0]; w1 = sc * wp[1]; w2 = sc * wp[2]; w3 = sc * wp[3];\
            }                                                                      \
            WIA = pk2(w0, w1);  WIB = pk2(w2, w3);                                 \
            const float* hp = w_hh + ((stage * 16) + r) * 4;                       \
            WHA = pk2(sc * hp[j ^ 0], sc * hp[j ^ 1]);                             \
            WHB = pk2(sc * hp[j ^ 2], sc * hp[j ^ 3]);                             \
            BP  = pk2(sc * (b_ih[stage * 16 + r] + b_hh[stage * 16 + r]), 0.0f);   \
        } while (0)
        LQ(0, wiA0, wiB0, whA0, whB0, bp0);
        LQ(1, wiA1, wiB1, whA1, whB1, bp1);
        LQ(2, wiA2, wiB2, whA2, whB2, bp2);
        LQ(3, wiA3, wiB3, whA3, whB3, bp3);
        #undef LQ
    } else if (stage == 5) {
        wiA0 = pk2(w_lin[0], w_lin[1]);
        wiB0 = pk2(w_lin[2], w_lin[3]);
        bp0  = pk2(b_lin[0], 0.0f);
    }

    // ---- SMEM staging: x row (zero-padded) + w_fc rows (5-entry zero head) ----
    __shared__ float2 xs2[SEQ + 8];              // [0..609]=x, rest 0
    __shared__ float  wfc_s[5][SEQ + 16];        // row idx ss: [5..614]=w_fc[ss-5]
    {
        const float2* xb2 = reinterpret_cast<const float2*>(x + (size_t)b * SEQ * 2);
        for (int i = lane; i < SEQ + 8; i += 32)
            xs2[i] = (i < SEQ) ? xb2[i] : make_float2(0.0f, 0.0f);
        #pragma unroll
        for (int r = 0; r < 5; ++r)
            for (int i = lane; i < SEQ + 16; i += 32)
                wfc_s[r][i] = (i >= 5 && i < SEQ + 5) ? w_fc[r * SEQ + (i - 5)] : 0.0f;
    }
    __syncwarp();

    const float* wA = wfc_s[(stage == 5) ? j : 0];   // per-lane FC row
    const float* w4 = wfc_s[4];

    float accA = (stage == 5) ? b_fc[j] : 0.0f;
    float accB = (lane == 20) ? b_fc[4] : 0.0f;

    // ---- state ----
    float hpub = (lane == 28) ? xs2[0].x : ((lane == 29) ? xs2[0].y : 0.0f);
    float cj = 0.0f;

    #define STEP(ss, GUARD) do {                                                   \
        const float2 xv = xs2[(ss) + 1];                                           \
        const float h0 = hpub;                                                     \
        const float h1 = __shfl_xor_sync(0xffffffffu, hpub, 1);                    \
        const float h2 = __shfl_xor_sync(0xffffffffu, hpub, 2);                    \
        const float h3 = __shfl_xor_sync(0xffffffffu, hpub, 3);                    \
        const float p0 = __shfl_sync(0xffffffffu, hpub, pbase);                    \
        const float p1 = __shfl_sync(0xffffffffu, hpub, pbase + 1);                \
        const float p2 = __shfl_sync(0xffffffffu, hpub, pbase + 2);                \
        const float p3 = __shfl_sync(0xffffffffu, hpub, pbase + 3);                \
        const ull hA = pk2(h0, h1), hB = pk2(h2, h3);                              \
        const ull pA = pk2(p0, p1), pB = pk2(p2, p3);                              \
        const float g0 = hadd2(fma2(whB0, hB, fma2(whA0, hA,                       \
                               fma2(wiB0, pB, fma2(wiA0, pA, bp0)))));             \
        const float g1 = hadd2(fma2(whB1, hB, fma2(whA1, hA,                       \
                               fma2(wiB1, pB, fma2(wiA1, pA, bp1)))));             \
        const float g2 = hadd2(fma2(whB2, hB, fma2(whA2, hA,                       \
                               fma2(wiB2, pB, fma2(wiA2, pA, bp2)))));             \
        const float g3 = hadd2(fma2(whB3, hB, fma2(whA3, hA,                       \
                               fma2(wiB3, pB, fma2(wiA3, pA, bp3)))));             \
        const float gt = tanh_fast(g2);                                            \
        const float ig = fmaf(0.5f, tanh_fast(g0), 0.5f);                          \
        const float fg = fmaf(0.5f, tanh_fast(g1), 0.5f);                          \
        const float og = fmaf(0.5f, tanh_fast(g3), 0.5f);                          \
        const float cn = fmaf(fg, cj, ig * gt);                                    \
        const float hn = og * tanh_fast(cn);                                       \
        float xc = (lane & 1) ? xv.y : xv.x;                                       \
        xc = (lane & 2) ? 0.0f : xc;                                               \
        if (GUARD) {                                                               \
            const bool tv = (unsigned)((ss) - stage) < (unsigned)SEQ;              \
            cj = tv ? cn : cj;                                                     \
            const float hc = tv ? hn : hpub;                                       \
            hpub = isX ? xc : hc;                                                  \
        } else {                                                                   \
            cj = cn;                                                               \
            hpub = isX ? xc : hn;                                                  \
        }                                                                          \
        accA = fmaf(wA[(ss)], g0, accA);                                           \
        accB = fmaf(w4[(ss)], g0, accB);                                           \
    } while (0)

    // prologue: validity selects active
    #pragma unroll 1
    for (int ss = 0; ss < 5; ++ss) STEP(ss, true);
    // steady + epilogue: select-free (zero-padded x / w_fc rows make
    // head/tail contributions exact zeros; garbage never reaches a
    // valid consumer)
    #pragma unroll 1
    for (int ss = 5; ss < NSTEP; ++ss) STEP(ss, false);

    #undef STEP

    if (stage == 5) out[b * 5 + j] = accA;
    if (lane == 20) out[b * 5 + 4] = accB;
}

extern "C" void kernel_launch(void* const* d_in, const int* in_sizes, int n_in,
                              void* d_out, int out_size) {
    const float* x     = (const float*)d_in[0];
    const float* w_ih0 = (const float*)d_in[1];
    const float* w_ih  = (const float*)d_in[2];
    const float* w_hh  = (const float*)d_in[3];
    const float* b_ih  = (const float*)d_in[4];
    const float* b_hh  = (const float*)d_in[5];
    const float* w_lin = (const float*)d_in[6];
    const float* b_lin = (const float*)d_in[7];
    const float* w_fc  = (const float*)d_in[8];
    const float* b_fc  = (const float*)d_in[9];
    float* out = (float*)d_out;

    lstm_warp_kernel<<<BATCH, 32>>>(
        x, w_ih0, w_ih, w_hh, b_ih, b_hh, w_lin, b_lin, w_fc, b_fc, out);
}

// round 9
// speedup vs baseline: 1.4595x; 1.0238x over previous
#include <cuda_runtime.h>
#include <cuda_bf16.h>

// RNN_72541997629806: 5-layer stacked LSTM (H=4), SEQ=610, BATCH=128,
// per-t Linear(4->1) + final FC [5,610] -> out [128,5].
//
// R9: one warp = one batch element; systolic pipeline processing TWO
//   timesteps per shuffle round (lag 2 per stage). lane = stage*4 + j:
//   stages 0-4 LSTM layers, stage 5 Linear+FC, lanes 28-31 x-injection
//   (publish x components for both round timesteps as hpubA/hpubB).
//   14 shuffles / 2 steps; packed fma.rn.f32x2 gate trees; x + w_fc in
//   SMEM (zero-padded; wfc rows have 10-entry zero head for lag-10 FC).

#define SEQ 610
#define BATCH 128
#define ROUNDS 310           // r = 0..309 ; stage5 t1 = 2*309-10+1 = 609
#define XS_N 624
#define WFC_N 624            // valid data at [10, 620)

typedef unsigned long long ull;

__device__ __forceinline__ float tanh_fast(float x) {
    float y;
    asm("tanh.approx.f32 %0, %1;" : "=f"(y) : "f"(x));
    return y;
}
__device__ __forceinline__ ull pk2(float lo, float hi) {
    ull r; asm("mov.b64 %0, {%1, %2};" : "=l"(r) : "f"(lo), "f"(hi)); return r;
}
__device__ __forceinline__ ull fma2(ull a, ull b, ull c) {
    ull d; asm("fma.rn.f32x2 %0, %1, %2, %3;" : "=l"(d) : "l"(a), "l"(b), "l"(c)); return d;
}
__device__ __forceinline__ ull mul2(ull a, ull b) {
    ull d; asm("mul.rn.f32x2 %0, %1, %2;" : "=l"(d) : "l"(a), "l"(b)); return d;
}
__device__ __forceinline__ ull add2(ull a, ull b) {
    ull d; asm("add.rn.f32x2 %0, %1, %2;" : "=l"(d) : "l"(a), "l"(b)); return d;
}
__device__ __forceinline__ float hadd2(ull v) {
    float lo, hi; asm("mov.b64 {%0, %1}, %2;" : "=f"(lo), "=f"(hi) : "l"(v)); return lo + hi;
}

__global__ __launch_bounds__(32, 1)
void lstm_warp_kernel(const float* __restrict__ x,      // [128,610,2]
                      const float* __restrict__ w_ih0,  // [16,2]
                      const float* __restrict__ w_ih,   // [4,16,4]
                      const float* __restrict__ w_hh,   // [5,16,4]
                      const float* __restrict__ b_ih,   // [5,16]
                      const float* __restrict__ b_hh,   // [5,16]
                      const float* __restrict__ w_lin,  // [1,4]
                      const float* __restrict__ b_lin,  // [1]
                      const float* __restrict__ w_fc,   // [5,610]
                      const float* __restrict__ b_fc,   // [5]
                      float* __restrict__ out)          // [128,5]
{
    const int lane  = threadIdx.x;
    const int stage = lane >> 2;             // 0..7
    const int j     = lane & 3;
    const int b     = blockIdx.x;
    const int pbase = (lane - 4) & 28;       // base lane of previous stage quad
    const bool isX  = (lane >= 28);

    // ---- packed per-lane weights (i/f/o pre-scaled 0.5, sigmoid-via-tanh) ----
    ull wiA0=0,wiA1=0,wiA2=0,wiA3=0, wiB0=0,wiB1=0,wiB2=0,wiB3=0;
    ull whA0=0,whA1=0,whA2=0,whA3=0, whB0=0,whB1=0,whB2=0,whB3=0;
    ull bp0=0, bp1=0, bp2=0, bp3=0;

    if (stage <= 4) {
        #define LQ(q, WIA, WIB, WHA, WHB, BP) do {                                 \
            const int   r  = (q) * 4 + j;                                          \
            const float sc = ((q) == 2) ? 1.0f : 0.5f;                             \
            float w0, w1, w2, w3;                                                  \
            if (stage == 0) {                                                      \
                w0 = sc * w_ih0[r * 2 + 0];  w1 = sc * w_ih0[r * 2 + 1];           \
                w2 = 0.0f;                   w3 = 0.0f;                            \
            } else {                                                               \
                const float* wp = w_ih + (((stage - 1) * 16) + r) * 4;             \
                w0 = sc * wp[0]; w1 = sc * wp[1]; w2 = sc * wp[2]; w3 = sc * wp[3];\
            }                                                                      \
            WIA = pk2(w0, w1);  WIB = pk2(w2, w3);                                 \
            const float* hp = w_hh + ((stage * 16) + r) * 4;                       \
            WHA = pk2(sc * hp[j ^ 0], sc * hp[j ^ 1]);                             \
            WHB = pk2(sc * hp[j ^ 2], sc * hp[j ^ 3]);                             \
            BP  = pk2(sc * (b_ih[stage * 16 + r] + b_hh[stage * 16 + r]), 0.0f);   \
        } while (0)
        LQ(0, wiA0, wiB0, whA0, whB0, bp0);
        LQ(1, wiA1, wiB1, whA1, whB1, bp1);
        LQ(2, wiA2, wiB2, whA2, whB2, bp2);
        LQ(3, wiA3, wiB3, whA3, whB3, bp3);
        #undef LQ
    } else if (stage == 5) {
        wiA0 = pk2(w_lin[0], w_lin[1]);
        wiB0 = pk2(w_lin[2], w_lin[3]);
        bp0  = pk2(b_lin[0], 0.0f);
    }

    // ---- SMEM staging ----
    __shared__ float2 xs2[XS_N];            // [0..609]=x, rest 0
    __shared__ float  wfc_s[5][WFC_N];      // [10..619]=w_fc row, rest 0
    {
        const float2* xb2 = reinterpret_cast<const float2*>(x + (size_t)b * SEQ * 2);
        for (int i = lane; i < XS_N; i += 32)
            xs2[i] = (i < SEQ) ? xb2[i] : make_float2(0.0f, 0.0f);
        #pragma unroll
        for (int r = 0; r < 5; ++r)
            for (int i = lane; i < WFC_N; i += 32)
                wfc_s[r][i] = (i >= 10 && i < SEQ + 10) ? w_fc[r * SEQ + (i - 10)] : 0.0f;
    }
    __syncwarp();

    const float* wA = wfc_s[(stage == 5) ? j : 0];
    const float* w4 = wfc_s[4];
    float accA = (stage == 5) ? b_fc[j] : 0.0f;
    float accB = (lane == 20) ? b_fc[4] : 0.0f;

    // ---- state: hpubA/hpubB = published h for the round's two timesteps ----
    float hpubA, hpubB, cj = 0.0f;
    {
        const float2 xv0 = xs2[0], xv1 = xs2[1];
        float xcA = (lane & 1) ? xv0.y : xv0.x;  xcA = (lane & 2) ? 0.0f : xcA;
        float xcB = (lane & 1) ? xv1.y : xv1.x;  xcB = (lane & 2) ? 0.0f : xcB;
        hpubA = isX ? xcA : 0.0f;
        hpubB = isX ? xcB : 0.0f;
    }

    // one LSTM cell: packed inputs PA/PB (prev-stage quad), HA/HB (own quad)
    #define CELL(PA, PB, HA, HB, CN, HN, G0OUT) do {                               \
        const float g0 = hadd2(add2(fma2(whA0, HA, fma2(wiA0, PA, bp0)),           \
                                    fma2(whB0, HB, mul2(wiB0, PB))));              \
        const float g1 = hadd2(add2(fma2(whA1, HA, fma2(wiA1, PA, bp1)),           \
                                    fma2(whB1, HB, mul2(wiB1, PB))));              \
        const float g2 = hadd2(add2(fma2(whA2, HA, fma2(wiA2, PA, bp2)),           \
                                    fma2(whB2, HB, mul2(wiB2, PB))));              \
        const float g3 = hadd2(add2(fma2(whA3, HA, fma2(wiA3, PA, bp3)),           \
                                    fma2(whB3, HB, mul2(wiB3, PB))));              \
        const float gt = tanh_fast(g2);                                            \
        const float ig = fmaf(0.5f, tanh_fast(g0), 0.5f);                          \
        const float fg = fmaf(0.5f, tanh_fast(g1), 0.5f);                          \
        const float og = fmaf(0.5f, tanh_fast(g3), 0.5f);                          \
        CN = fmaf(fg, cj, ig * gt);                                                \
        HN = og * tanh_fast(CN);                                                   \
        G0OUT = g0;                                                                \
    } while (0)

    // one round = two timesteps t0 = 2r - 2*stage, t1 = t0+1
    #define ROUND(r, GUARD) do {                                                   \
        const int i0 = 2 * (r);                                                    \
        /* round-start shuffles (all parallel off hpubA/hpubB) */                  \
        const float ob1 = __shfl_xor_sync(0xffffffffu, hpubB, 1);                  \
        const float ob2 = __shfl_xor_sync(0xffffffffu, hpubB, 2);                  \
        const float ob3 = __shfl_xor_sync(0xffffffffu, hpubB, 3);                  \
        const float pA0 = __shfl_sync(0xffffffffu, hpubA, pbase);                  \
        const float pA1 = __shfl_sync(0xffffffffu, hpubA, pbase + 1);              \
        const float pA2 = __shfl_sync(0xffffffffu, hpubA, pbase + 2);              \
        const float pA3 = __shfl_sync(0xffffffffu, hpubA, pbase + 3);              \
        const float pB0 = __shfl_sync(0xffffffffu, hpubB, pbase);                  \
        const float pB1 = __shfl_sync(0xffffffffu, hpubB, pbase + 1);              \
        const float pB2 = __shfl_sync(0xffffffffu, hpubB, pbase + 2);              \
        const float pB3 = __shfl_sync(0xffffffffu, hpubB, pbase + 3);              \
        /* cell t0: own h quad = (hpubB, ob1..3) = h(t0-1) */                      \
        float cn0, hn0, g0c0;                                                      \
        CELL(pk2(pA0, pA1), pk2(pA2, pA3), pk2(hpubB, ob1), pk2(ob2, ob3),         \
             cn0, hn0, g0c0);                                                      \
        float hAn;                                                                 \
        if (GUARD) {                                                               \
            const bool tv = (r) >= stage;                                          \
            cj  = tv ? cn0 : cj;                                                   \
            hAn = tv ? hn0 : 0.0f;                                                 \
        } else { cj = cn0; hAn = hn0; }                                            \
        /* intra-round gather of h(t0) */                                          \
        const float a1 = __shfl_xor_sync(0xffffffffu, hAn, 1);                     \
        const float a2 = __shfl_xor_sync(0xffffffffu, hAn, 2);                     \
        const float a3 = __shfl_xor_sync(0xffffffffu, hAn, 3);                     \
        /* cell t1 */                                                              \
        float cn1, hn1, g0c1;                                                      \
        CELL(pk2(pB0, pB1), pk2(pB2, pB3), pk2(hAn, a1), pk2(a2, a3),              \
             cn1, hn1, g0c1);                                                      \
        float hBn;                                                                 \
        if (GUARD) {                                                               \
            const bool tv = (r) >= stage;                                          \
            cj  = tv ? cn1 : cj;                                                   \
            hBn = tv ? hn1 : 0.0f;                                                 \
        } else { cj = cn1; hBn = hn1; }                                            \
        /* FC accumulate (stage5 g0 = Linear preactivation; zero-headed wfc) */    \
        accA = fmaf(wA[i0],     g0c0, accA);                                       \
        accA = fmaf(wA[i0 + 1], g0c1, accA);                                       \
        accB = fmaf(w4[i0],     g0c0, accB);                                       \
        accB = fmaf(w4[i0 + 1], g0c1, accB);                                       \
        /* injection publish for next round (x(2r+2), x(2r+3)) */                  \
        const float2 xv0 = xs2[i0 + 2], xv1 = xs2[i0 + 3];                         \
        float xcA = (lane & 1) ? xv0.y : xv0.x;  xcA = (lane & 2) ? 0.0f : xcA;    \
        float xcB = (lane & 1) ? xv1.y : xv1.x;  xcB = (lane & 2) ? 0.0f : xcB;    \
        hpubA = isX ? xcA : hAn;                                                   \
        hpubB = isX ? xcB : hBn;                                                   \
    } while (0)

    // prologue: guarded (t0 < 0 for stage > r)
    #pragma unroll 1
    for (int r = 0; r < 5; ++r) ROUND(r, true);
    // steady + tail: select-free (zero-padded x and wfc rows absorb overrun)
    #pragma unroll 2
    for (int r = 5; r < ROUNDS; ++r) ROUND(r, false);

    #undef ROUND
    #undef CELL

    if (stage == 5) out[b * 5 + j] = accA;
    if (lane == 20) out[b * 5 + 4] = accB;
}

extern "C" void kernel_launch(void* const* d_in, const int* in_sizes, int n_in,
                              void* d_out, int out_size) {
    const float* x     = (const float*)d_in[0];
    const float* w_ih0 = (const float*)d_in[1];
    const float* w_ih  = (const float*)d_in[2];
    const float* w_hh  = (const float*)d_in[3];
    const float* b_ih  = (const float*)d_in[4];
    const float* b_hh  = (const float*)d_in[5];
    const float* w_lin = (const float*)d_in[6];
    const float* b_lin = (const float*)d_in[7];
    const float* w_fc  = (const float*)d_in[8];
    const float* b_fc  = (const float*)d_in[9];
    float* out = (float*)d_out;

    lstm_warp_kernel<<<BATCH, 32>>>(
        x, w_ih0, w_ih, w_hh, b_ih, b_hh, w_lin, b_lin, w_fc, b_fc, out);
}